// round 1
// baseline (speedup 1.0000x reference)
#include <cuda_runtime.h>
#include <math.h>

// Problem constants (fixed by the reference)
#define NB   2          // batch
#define SS   2048       // sequence
#define DMODEL 1024
#define NH   16
#define DKH  64
#define MTOT (NB*SS)    // 4096 rows

// Scratch (allocation-free rule: __device__ globals)
__device__ float g_Qh[NB*NH*SS*DKH];   // [B,H,S,Dk]
__device__ float g_Kh[NB*NH*SS*DKH];
__device__ float g_Vh[NB*NH*SS*DKH];
__device__ float g_ctx[MTOT*DMODEL];   // [B,S,H*Dk]

// ---------------------------------------------------------------------------
// FFMA-only expf (avoids MUFU bottleneck: 134M exps in softmax).
// exp(x) = 2^(x*log2e); round via +1.5*2^23 trick; degree-5 poly on [-0.5,0.5];
// scale by exponent splice. Valid for x <= 0 (softmax guarantees), clamped low.
// ---------------------------------------------------------------------------
__device__ __forceinline__ float fexp(float x) {
    x = fmaxf(x, -80.0f);
    float y  = x * 1.4426950408889634f;
    float t  = y + 12582912.0f;       // 1.5*2^23: forces round-to-nearest-int
    float fn = t - 12582912.0f;
    float f  = y - fn;                // f in [-0.5, 0.5]
    int   n  = (int)fn;
    float sc = __int_as_float((n + 127) << 23);
    float p  = 1.3333558146e-3f;
    p = fmaf(p, f, 9.6181291076e-3f);
    p = fmaf(p, f, 5.5504108664e-2f);
    p = fmaf(p, f, 2.4022650696e-1f);
    p = fmaf(p, f, 6.9314718056e-1f);
    p = fmaf(p, f, 1.0f);
    return p * sc;
}

// ---------------------------------------------------------------------------
// SGEMM: C[M=4096, N=1024] = A[4096,1024] @ B[1024,1024] + bias
// 128x128 block tile, BK=16, 256 threads, 8x8 per-thread micro-tile.
// SPLIT: scatter output into per-head layout [B,H,S,Dk] (col = h*64+d).
// ---------------------------------------------------------------------------
template<bool SPLIT>
__global__ __launch_bounds__(256, 2)
void gemm128(const float* __restrict__ A, const float* __restrict__ Bm,
             const float* __restrict__ bias, float* __restrict__ C)
{
    const int K = DMODEL, N = DMODEL;
    __shared__ float As[16][132];   // [k][m], padded to dodge bank conflicts
    __shared__ float Bs[16][132];   // [k][n]

    const int tid = threadIdx.x;
    const int bm  = blockIdx.y * 128;
    const int bn  = blockIdx.x * 128;
    const int ty  = tid >> 4;       // 0..15 -> rows ty*8..
    const int tx  = tid & 15;       // 0..15 -> cols tx*8..

    float acc[8][8];
    #pragma unroll
    for (int i = 0; i < 8; i++)
        #pragma unroll
        for (int j = 0; j < 8; j++) acc[i][j] = 0.0f;

    const int arow = tid >> 2;          // 0..63 (plus +64 row)
    const int acol = (tid & 3) << 2;    // 0,4,8,12
    const int brow = tid >> 5;          // 0..7 (plus +8 row)
    const int bcol = (tid & 31) << 2;   // 0..124

    const float* Ab = A + (size_t)bm * K;
    const float* Bb = Bm + bn;

    for (int k0 = 0; k0 < K; k0 += 16) {
        float4 a0 = *(const float4*)(Ab + (size_t)arow        * K + k0 + acol);
        float4 a1 = *(const float4*)(Ab + (size_t)(arow + 64) * K + k0 + acol);
        As[acol+0][arow]    = a0.x; As[acol+1][arow]    = a0.y;
        As[acol+2][arow]    = a0.z; As[acol+3][arow]    = a0.w;
        As[acol+0][arow+64] = a1.x; As[acol+1][arow+64] = a1.y;
        As[acol+2][arow+64] = a1.z; As[acol+3][arow+64] = a1.w;
        float4 b0 = *(const float4*)(Bb + (size_t)(k0 + brow)     * N + bcol);
        float4 b1 = *(const float4*)(Bb + (size_t)(k0 + brow + 8) * N + bcol);
        *(float4*)&Bs[brow][bcol]   = b0;
        *(float4*)&Bs[brow+8][bcol] = b1;
        __syncthreads();

        #pragma unroll
        for (int k = 0; k < 16; k++) {
            float ra[8], rb[8];
            *(float4*)&ra[0] = *(const float4*)&As[k][ty*8];
            *(float4*)&ra[4] = *(const float4*)&As[k][ty*8+4];
            *(float4*)&rb[0] = *(const float4*)&Bs[k][tx*8];
            *(float4*)&rb[4] = *(const float4*)&Bs[k][tx*8+4];
            #pragma unroll
            for (int i = 0; i < 8; i++)
                #pragma unroll
                for (int j = 0; j < 8; j++)
                    acc[i][j] = fmaf(ra[i], rb[j], acc[i][j]);
        }
        __syncthreads();
    }

    float bz[8];
    #pragma unroll
    for (int j = 0; j < 8; j++) bz[j] = bias[bn + tx*8 + j];

    #pragma unroll
    for (int i = 0; i < 8; i++) {
        int row = bm + ty*8 + i;
        #pragma unroll
        for (int j = 0; j < 8; j++) acc[i][j] += bz[j];
        if (SPLIT) {
            int b = row >> 11, s = row & (SS - 1);
            int col0 = bn + tx*8;
            int h = col0 >> 6, d0 = col0 & 63;   // 8 cols never cross a 64-boundary
            float* dst = C + ((size_t)((b*NH + h)*SS + s)) * DKH + d0;
            *(float4*)dst     = make_float4(acc[i][0], acc[i][1], acc[i][2], acc[i][3]);
            *(float4*)(dst+4) = make_float4(acc[i][4], acc[i][5], acc[i][6], acc[i][7]);
        } else {
            float* dst = C + (size_t)row * N + bn + tx*8;
            *(float4*)dst     = make_float4(acc[i][0], acc[i][1], acc[i][2], acc[i][3]);
            *(float4*)(dst+4) = make_float4(acc[i][4], acc[i][5], acc[i][6], acc[i][7]);
        }
    }
}

// ---------------------------------------------------------------------------
// Flash attention, fp32. Br=Bc=64, Dk=64. 256 threads as 16x16; each thread
// owns a 4x4 tile of scores/output. Row softmax state (m,l) lives in regs,
// replicated across the 16 lanes that share a row group (shfl reductions).
// Output written directly in [B,S,H*Dk] layout for the final GEMM.
// ---------------------------------------------------------------------------
__global__ __launch_bounds__(256)
void attn64(const float* __restrict__ Qh, const float* __restrict__ Kh,
            const float* __restrict__ Vh, float* __restrict__ ctx)
{
    extern __shared__ float sm[];
    float* Qst = sm;              // [d][r]  64x65
    float* Kst = sm + 64*65;      // [d][c]  64x65
    float* Vs  = sm + 2*64*65;    // [c][d]  64x65
    float* Pst = sm + 3*64*65;    // [c][r]  64x65

    const int tid = threadIdx.x;
    const int qt = blockIdx.x, h = blockIdx.y, b = blockIdx.z;
    const int ty = tid >> 4, tx = tid & 15;
    const float scale = 0.125f;   // 1/sqrt(64)

    const size_t headoff = ((size_t)(b*NH + h)) * SS * DKH;
    const float* Qg = Qh + headoff + (size_t)qt * 64 * DKH;
    const float* Kg = Kh + headoff;
    const float* Vg = Vh + headoff;

    // Q tile, transposed into [d][r]
    for (int idx = tid; idx < 64*64; idx += 256) {
        int r = idx >> 6, d = idx & 63;
        Qst[d*65 + r] = Qg[idx];
    }
    __syncthreads();

    float m[4], l[4], O[4][4];
    #pragma unroll
    for (int i = 0; i < 4; i++) {
        m[i] = -1e30f; l[i] = 0.0f;
        #pragma unroll
        for (int j = 0; j < 4; j++) O[i][j] = 0.0f;
    }

    for (int kt = 0; kt < SS/64; kt++) {
        const float* Kt = Kg + (size_t)kt * 64 * DKH;
        const float* Vt = Vg + (size_t)kt * 64 * DKH;
        for (int idx = tid; idx < 64*64; idx += 256) {
            int c = idx >> 6, d = idx & 63;
            Kst[d*65 + c] = Kt[idx];
            Vs[c*65 + d]  = Vt[idx];
        }
        __syncthreads();

        // S = Q @ K^T (4x4 per thread)
        float s4[4][4];
        #pragma unroll
        for (int i = 0; i < 4; i++)
            #pragma unroll
            for (int j = 0; j < 4; j++) s4[i][j] = 0.0f;

        #pragma unroll 4
        for (int d = 0; d < 64; d++) {
            float ra[4], rb[4];
            #pragma unroll
            for (int i = 0; i < 4; i++) ra[i] = Qst[d*65 + ty*4 + i];
            #pragma unroll
            for (int j = 0; j < 4; j++) rb[j] = Kst[d*65 + tx*4 + j];
            #pragma unroll
            for (int i = 0; i < 4; i++)
                #pragma unroll
                for (int j = 0; j < 4; j++)
                    s4[i][j] = fmaf(ra[i], rb[j], s4[i][j]);
        }

        // online softmax per row (16-lane shfl groups; bit4 of lane untouched)
        #pragma unroll
        for (int i = 0; i < 4; i++) {
            float tm = -1e30f;
            #pragma unroll
            for (int j = 0; j < 4; j++) {
                s4[i][j] *= scale;
                tm = fmaxf(tm, s4[i][j]);
            }
            #pragma unroll
            for (int off = 8; off >= 1; off >>= 1)
                tm = fmaxf(tm, __shfl_xor_sync(0xffffffffu, tm, off));
            float mn = fmaxf(m[i], tm);
            float ps = 0.0f;
            #pragma unroll
            for (int j = 0; j < 4; j++) {
                float p = fexp(s4[i][j] - mn);
                s4[i][j] = p;
                ps += p;
            }
            #pragma unroll
            for (int off = 8; off >= 1; off >>= 1)
                ps += __shfl_xor_sync(0xffffffffu, ps, off);
            float fac = fexp(m[i] - mn);
            l[i] = l[i]*fac + ps;
            m[i] = mn;
            #pragma unroll
            for (int j = 0; j < 4; j++) O[i][j] *= fac;
            #pragma unroll
            for (int j = 0; j < 4; j++)
                Pst[(tx*4 + j)*65 + ty*4 + i] = s4[i][j];
        }
        __syncthreads();

        // O += P @ V
        #pragma unroll 4
        for (int c = 0; c < 64; c++) {
            float rp[4], rv[4];
            #pragma unroll
            for (int i = 0; i < 4; i++) rp[i] = Pst[c*65 + ty*4 + i];
            #pragma unroll
            for (int j = 0; j < 4; j++) rv[j] = Vs[c*65 + tx*4 + j];
            #pragma unroll
            for (int i = 0; i < 4; i++)
                #pragma unroll
                for (int j = 0; j < 4; j++)
                    O[i][j] = fmaf(rp[i], rv[j], O[i][j]);
        }
        __syncthreads();  // protect Kst/Vs/Pst before next tile's loads
    }

    // normalize and write [B,S,H*Dk]
    #pragma unroll
    for (int i = 0; i < 4; i++) {
        float inv = 1.0f / l[i];
        int s = qt*64 + ty*4 + i;
        float* dst = ctx + ((size_t)(b*SS + s)) * DMODEL + h*DKH + tx*4;
        *(float4*)dst = make_float4(O[i][0]*inv, O[i][1]*inv, O[i][2]*inv, O[i][3]*inv);
    }
}

// ---------------------------------------------------------------------------
extern "C" void kernel_launch(void* const* d_in, const int* in_sizes, int n_in,
                              void* d_out, int out_size)
{
    const float* q  = (const float*)d_in[0];
    const float* k  = (const float*)d_in[1];
    const float* v  = (const float*)d_in[2];
    const float* Wq = (const float*)d_in[3];
    const float* bq = (const float*)d_in[4];
    const float* Wk = (const float*)d_in[5];
    const float* bk = (const float*)d_in[6];
    const float* Wv = (const float*)d_in[7];
    const float* bv = (const float*)d_in[8];
    const float* Wo = (const float*)d_in[9];
    const float* bo = (const float*)d_in[10];
    float* out = (float*)d_out;

    float *Qh, *Kh, *Vh, *ctx;
    cudaGetSymbolAddress((void**)&Qh,  g_Qh);
    cudaGetSymbolAddress((void**)&Kh,  g_Kh);
    cudaGetSymbolAddress((void**)&Vh,  g_Vh);
    cudaGetSymbolAddress((void**)&ctx, g_ctx);

    const int smem = 4 * 64 * 65 * (int)sizeof(float);  // 66560 B
    cudaFuncSetAttribute(attn64, cudaFuncAttributeMaxDynamicSharedMemorySize, smem);

    dim3 gg(DMODEL/128, MTOT/128);   // (8, 32)
    gemm128<true ><<<gg, 256>>>(q,   Wq, bq, Qh);
    gemm128<true ><<<gg, 256>>>(k,   Wk, bk, Kh);
    gemm128<true ><<<gg, 256>>>(v,   Wv, bv, Vh);
    attn64<<<dim3(SS/64, NH, NB), 256, smem>>>(Qh, Kh, Vh, ctx);
    gemm128<false><<<gg, 256>>>(ctx, Wo, bo, out);
}

// round 2
// speedup vs baseline: 1.0009x; 1.0009x over previous
#include <cuda_runtime.h>
#include <math.h>

// Problem constants (fixed by the reference)
#define NB   2          // batch
#define SS   2048       // sequence
#define DMODEL 1024
#define NH   16
#define DKH  64
#define MTOT (NB*SS)    // 4096 rows

// Scratch (allocation-free rule: __device__ globals)
__device__ float g_Qh[NB*NH*SS*DKH];   // [B,H,S,Dk]
__device__ float g_Kh[NB*NH*SS*DKH];
__device__ float g_Vh[NB*NH*SS*DKH];
__device__ float g_ctx[MTOT*DMODEL];   // [B,S,H*Dk]

// ---------------------------------------------------------------------------
// FFMA-only expf (avoids MUFU bottleneck: 134M exps in softmax).
// exp(x) = 2^(x*log2e); round via +1.5*2^23 trick; degree-5 poly on [-0.5,0.5];
// scale by exponent splice. Valid for x <= 0 (softmax guarantees), clamped low.
// ---------------------------------------------------------------------------
__device__ __forceinline__ float fexp(float x) {
    x = fmaxf(x, -80.0f);
    float y  = x * 1.4426950408889634f;
    float t  = y + 12582912.0f;       // 1.5*2^23: forces round-to-nearest-int
    float fn = t - 12582912.0f;
    float f  = y - fn;                // f in [-0.5, 0.5]
    int   n  = (int)fn;
    float sc = __int_as_float((n + 127) << 23);
    float p  = 1.3333558146e-3f;
    p = fmaf(p, f, 9.6181291076e-3f);
    p = fmaf(p, f, 5.5504108664e-2f);
    p = fmaf(p, f, 2.4022650696e-1f);
    p = fmaf(p, f, 6.9314718056e-1f);
    p = fmaf(p, f, 1.0f);
    return p * sc;
}

// ---------------------------------------------------------------------------
// SGEMM: C[M=4096, N=1024] = A[4096,1024] @ B[1024,1024] + bias
// 128x128 block tile, BK=16, 256 threads, 8x8 per-thread micro-tile.
// SPLIT: scatter output into per-head layout [B,H,S,Dk] (col = h*64+d).
// ---------------------------------------------------------------------------
template<bool SPLIT>
__global__ __launch_bounds__(256, 2)
void gemm128(const float* __restrict__ A, const float* __restrict__ Bm,
             const float* __restrict__ bias, float* __restrict__ C)
{
    const int K = DMODEL, N = DMODEL;
    __shared__ float As[16][132];   // [k][m], padded to dodge bank conflicts
    __shared__ float Bs[16][132];   // [k][n]

    const int tid = threadIdx.x;
    const int bm  = blockIdx.y * 128;
    const int bn  = blockIdx.x * 128;
    const int ty  = tid >> 4;       // 0..15 -> rows ty*8..
    const int tx  = tid & 15;       // 0..15 -> cols tx*8..

    float acc[8][8];
    #pragma unroll
    for (int i = 0; i < 8; i++)
        #pragma unroll
        for (int j = 0; j < 8; j++) acc[i][j] = 0.0f;

    const int arow = tid >> 2;          // 0..63 (plus +64 row)
    const int acol = (tid & 3) << 2;    // 0,4,8,12
    const int brow = tid >> 5;          // 0..7 (plus +8 row)
    const int bcol = (tid & 31) << 2;   // 0..124

    const float* Ab = A + (size_t)bm * K;
    const float* Bb = Bm + bn;

    for (int k0 = 0; k0 < K; k0 += 16) {
        float4 a0 = *(const float4*)(Ab + (size_t)arow        * K + k0 + acol);
        float4 a1 = *(const float4*)(Ab + (size_t)(arow + 64) * K + k0 + acol);
        As[acol+0][arow]    = a0.x; As[acol+1][arow]    = a0.y;
        As[acol+2][arow]    = a0.z; As[acol+3][arow]    = a0.w;
        As[acol+0][arow+64] = a1.x; As[acol+1][arow+64] = a1.y;
        As[acol+2][arow+64] = a1.z; As[acol+3][arow+64] = a1.w;
        float4 b0 = *(const float4*)(Bb + (size_t)(k0 + brow)     * N + bcol);
        float4 b1 = *(const float4*)(Bb + (size_t)(k0 + brow + 8) * N + bcol);
        *(float4*)&Bs[brow][bcol]   = b0;
        *(float4*)&Bs[brow+8][bcol] = b1;
        __syncthreads();

        #pragma unroll
        for (int k = 0; k < 16; k++) {
            float ra[8], rb[8];
            *(float4*)&ra[0] = *(const float4*)&As[k][ty*8];
            *(float4*)&ra[4] = *(const float4*)&As[k][ty*8+4];
            *(float4*)&rb[0] = *(const float4*)&Bs[k][tx*8];
            *(float4*)&rb[4] = *(const float4*)&Bs[k][tx*8+4];
            #pragma unroll
            for (int i = 0; i < 8; i++)
                #pragma unroll
                for (int j = 0; j < 8; j++)
                    acc[i][j] = fmaf(ra[i], rb[j], acc[i][j]);
        }
        __syncthreads();
    }

    float bz[8];
    #pragma unroll
    for (int j = 0; j < 8; j++) bz[j] = bias[bn + tx*8 + j];

    #pragma unroll
    for (int i = 0; i < 8; i++) {
        int row = bm + ty*8 + i;
        #pragma unroll
        for (int j = 0; j < 8; j++) acc[i][j] += bz[j];
        if (SPLIT) {
            int b = row >> 11, s = row & (SS - 1);
            int col0 = bn + tx*8;
            int h = col0 >> 6, d0 = col0 & 63;   // 8 cols never cross a 64-boundary
            float* dst = C + ((size_t)((b*NH + h)*SS + s)) * DKH + d0;
            *(float4*)dst     = make_float4(acc[i][0], acc[i][1], acc[i][2], acc[i][3]);
            *(float4*)(dst+4) = make_float4(acc[i][4], acc[i][5], acc[i][6], acc[i][7]);
        } else {
            float* dst = C + (size_t)row * N + bn + tx*8;
            *(float4*)dst     = make_float4(acc[i][0], acc[i][1], acc[i][2], acc[i][3]);
            *(float4*)(dst+4) = make_float4(acc[i][4], acc[i][5], acc[i][6], acc[i][7]);
        }
    }
}

// ---------------------------------------------------------------------------
// Flash attention, fp32. Br=Bc=64, Dk=64. 256 threads as 16x16; each thread
// owns a 4x4 tile of scores/output. Row softmax state (m,l) lives in regs,
// replicated across the 16 lanes that share a row group (shfl reductions).
// Output written directly in [B,S,H*Dk] layout for the final GEMM.
// ---------------------------------------------------------------------------
__global__ __launch_bounds__(256)
void attn64(const float* __restrict__ Qh, const float* __restrict__ Kh,
            const float* __restrict__ Vh, float* __restrict__ ctx)
{
    extern __shared__ float sm[];
    float* Qst = sm;              // [d][r]  64x65
    float* Kst = sm + 64*65;      // [d][c]  64x65
    float* Vs  = sm + 2*64*65;    // [c][d]  64x65
    float* Pst = sm + 3*64*65;    // [c][r]  64x65

    const int tid = threadIdx.x;
    const int qt = blockIdx.x, h = blockIdx.y, b = blockIdx.z;
    const int ty = tid >> 4, tx = tid & 15;
    const float scale = 0.125f;   // 1/sqrt(64)

    const size_t headoff = ((size_t)(b*NH + h)) * SS * DKH;
    const float* Qg = Qh + headoff + (size_t)qt * 64 * DKH;
    const float* Kg = Kh + headoff;
    const float* Vg = Vh + headoff;

    // Q tile, transposed into [d][r]
    for (int idx = tid; idx < 64*64; idx += 256) {
        int r = idx >> 6, d = idx & 63;
        Qst[d*65 + r] = Qg[idx];
    }
    __syncthreads();

    float m[4], l[4], O[4][4];
    #pragma unroll
    for (int i = 0; i < 4; i++) {
        m[i] = -1e30f; l[i] = 0.0f;
        #pragma unroll
        for (int j = 0; j < 4; j++) O[i][j] = 0.0f;
    }

    for (int kt = 0; kt < SS/64; kt++) {
        const float* Kt = Kg + (size_t)kt * 64 * DKH;
        const float* Vt = Vg + (size_t)kt * 64 * DKH;
        for (int idx = tid; idx < 64*64; idx += 256) {
            int c = idx >> 6, d = idx & 63;
            Kst[d*65 + c] = Kt[idx];
            Vs[c*65 + d]  = Vt[idx];
        }
        __syncthreads();

        // S = Q @ K^T (4x4 per thread)
        float s4[4][4];
        #pragma unroll
        for (int i = 0; i < 4; i++)
            #pragma unroll
            for (int j = 0; j < 4; j++) s4[i][j] = 0.0f;

        #pragma unroll 4
        for (int d = 0; d < 64; d++) {
            float ra[4], rb[4];
            #pragma unroll
            for (int i = 0; i < 4; i++) ra[i] = Qst[d*65 + ty*4 + i];
            #pragma unroll
            for (int j = 0; j < 4; j++) rb[j] = Kst[d*65 + tx*4 + j];
            #pragma unroll
            for (int i = 0; i < 4; i++)
                #pragma unroll
                for (int j = 0; j < 4; j++)
                    s4[i][j] = fmaf(ra[i], rb[j], s4[i][j]);
        }

        // online softmax per row (16-lane shfl groups; bit4 of lane untouched)
        #pragma unroll
        for (int i = 0; i < 4; i++) {
            float tm = -1e30f;
            #pragma unroll
            for (int j = 0; j < 4; j++) {
                s4[i][j] *= scale;
                tm = fmaxf(tm, s4[i][j]);
            }
            #pragma unroll
            for (int off = 8; off >= 1; off >>= 1)
                tm = fmaxf(tm, __shfl_xor_sync(0xffffffffu, tm, off));
            float mn = fmaxf(m[i], tm);
            float ps = 0.0f;
            #pragma unroll
            for (int j = 0; j < 4; j++) {
                float p = fexp(s4[i][j] - mn);
                s4[i][j] = p;
                ps += p;
            }
            #pragma unroll
            for (int off = 8; off >= 1; off >>= 1)
                ps += __shfl_xor_sync(0xffffffffu, ps, off);
            float fac = fexp(m[i] - mn);
            l[i] = l[i]*fac + ps;
            m[i] = mn;
            #pragma unroll
            for (int j = 0; j < 4; j++) O[i][j] *= fac;
            #pragma unroll
            for (int j = 0; j < 4; j++)
                Pst[(tx*4 + j)*65 + ty*4 + i] = s4[i][j];
        }
        __syncthreads();

        // O += P @ V
        #pragma unroll 4
        for (int c = 0; c < 64; c++) {
            float rp[4], rv[4];
            #pragma unroll
            for (int i = 0; i < 4; i++) rp[i] = Pst[c*65 + ty*4 + i];
            #pragma unroll
            for (int j = 0; j < 4; j++) rv[j] = Vs[c*65 + tx*4 + j];
            #pragma unroll
            for (int i = 0; i < 4; i++)
                #pragma unroll
                for (int j = 0; j < 4; j++)
                    O[i][j] = fmaf(rp[i], rv[j], O[i][j]);
        }
        __syncthreads();  // protect Kst/Vs/Pst before next tile's loads
    }

    // normalize and write [B,S,H*Dk]
    #pragma unroll
    for (int i = 0; i < 4; i++) {
        float inv = 1.0f / l[i];
        int s = qt*64 + ty*4 + i;
        float* dst = ctx + ((size_t)(b*SS + s)) * DMODEL + h*DKH + tx*4;
        *(float4*)dst = make_float4(O[i][0]*inv, O[i][1]*inv, O[i][2]*inv, O[i][3]*inv);
    }
}

// ---------------------------------------------------------------------------
extern "C" void kernel_launch(void* const* d_in, const int* in_sizes, int n_in,
                              void* d_out, int out_size)
{
    const float* q  = (const float*)d_in[0];
    const float* k  = (const float*)d_in[1];
    const float* v  = (const float*)d_in[2];
    const float* Wq = (const float*)d_in[3];
    const float* bq = (const float*)d_in[4];
    const float* Wk = (const float*)d_in[5];
    const float* bk = (const float*)d_in[6];
    const float* Wv = (const float*)d_in[7];
    const float* bv = (const float*)d_in[8];
    const float* Wo = (const float*)d_in[9];
    const float* bo = (const float*)d_in[10];
    float* out = (float*)d_out;

    float *Qh, *Kh, *Vh, *ctx;
    cudaGetSymbolAddress((void**)&Qh,  g_Qh);
    cudaGetSymbolAddress((void**)&Kh,  g_Kh);
    cudaGetSymbolAddress((void**)&Vh,  g_Vh);
    cudaGetSymbolAddress((void**)&ctx, g_ctx);

    const int smem = 4 * 64 * 65 * (int)sizeof(float);  // 66560 B
    cudaFuncSetAttribute(attn64, cudaFuncAttributeMaxDynamicSharedMemorySize, smem);

    dim3 gg(DMODEL/128, MTOT/128);   // (8, 32)
    gemm128<true ><<<gg, 256>>>(q,   Wq, bq, Qh);
    gemm128<true ><<<gg, 256>>>(k,   Wk, bk, Kh);
    gemm128<true ><<<gg, 256>>>(v,   Wv, bv, Vh);
    attn64<<<dim3(SS/64, NH, NB), 256, smem>>>(Qh, Kh, Vh, ctx);
    gemm128<false><<<gg, 256>>>(ctx, Wo, bo, out);
}

// round 4
// speedup vs baseline: 1.2260x; 1.2248x over previous
#include <cuda_runtime.h>
#include <cuda_bf16.h>
#include <math.h>
#include <cstdint>

// Problem constants
#define NB   2
#define SS   2048
#define DMODEL 1024
#define NH   16
#define DKH  64
#define MTOT (NB*SS)    // 4096

// ---------------- scratch (no allocs allowed) ----------------
__device__ float g_Qh[NB*NH*SS*DKH];
__device__ float g_Kh[NB*NH*SS*DKH];
__device__ float g_Vh[NB*NH*SS*DKH];
__device__ float g_ctx[MTOT*DMODEL];
__device__ __nv_bfloat16 g_Ahi[MTOT*DMODEL];   // activation hi/lo (reused per GEMM)
__device__ __nv_bfloat16 g_Alo[MTOT*DMODEL];
__device__ __nv_bfloat16 g_Bhi[DMODEL*DMODEL]; // weight^T [N][K] hi/lo
__device__ __nv_bfloat16 g_Blo[DMODEL*DMODEL];

// ---------------- PTX helpers (baseline ISA only, no tcgen05) --------------
__device__ __forceinline__ uint32_t smem_u32(const void* p) {
    uint32_t a;
    asm("{ .reg .u64 t; cvta.to.shared.u64 t, %1; cvt.u32.u64 %0, t; }" : "=r"(a) : "l"(p));
    return a;
}
__device__ __forceinline__ void cpasync16(uint32_t dst, const void* src) {
    asm volatile("cp.async.cg.shared.global [%0], [%1], 16;" :: "r"(dst), "l"(src));
}
__device__ __forceinline__ void cp_commit() { asm volatile("cp.async.commit_group;" ::: "memory"); }
__device__ __forceinline__ void cp_wait1()  { asm volatile("cp.async.wait_group 1;" ::: "memory"); }
__device__ __forceinline__ void cp_wait0()  { asm volatile("cp.async.wait_group 0;" ::: "memory"); }

__device__ __forceinline__ void ldsm4(uint32_t& r0, uint32_t& r1, uint32_t& r2, uint32_t& r3,
                                      uint32_t addr) {
    asm volatile("ldmatrix.sync.aligned.m8n8.x4.shared.b16 {%0,%1,%2,%3}, [%4];"
                 : "=r"(r0), "=r"(r1), "=r"(r2), "=r"(r3) : "r"(addr));
}
__device__ __forceinline__ void mma16816(float* c,
                                         uint32_t a0, uint32_t a1, uint32_t a2, uint32_t a3,
                                         uint32_t b0, uint32_t b1) {
    asm volatile("mma.sync.aligned.m16n8k16.row.col.f32.bf16.bf16.f32 "
                 "{%0,%1,%2,%3}, {%4,%5,%6,%7}, {%8,%9}, {%0,%1,%2,%3};"
                 : "+f"(c[0]), "+f"(c[1]), "+f"(c[2]), "+f"(c[3])
                 : "r"(a0), "r"(a1), "r"(a2), "r"(a3), "r"(b0), "r"(b1));
}

// ---------------- convert kernels ----------------
__device__ __forceinline__ void split2(float x, __nv_bfloat16& h, __nv_bfloat16& l) {
    h = __float2bfloat16_rn(x);
    l = __float2bfloat16_rn(x - __bfloat162float(h));
}

__global__ void cvt_act(const float* __restrict__ x, __nv_bfloat16* __restrict__ hi,
                        __nv_bfloat16* __restrict__ lo, int n4) {
    int i = blockIdx.x * blockDim.x + threadIdx.x;
    if (i >= n4) return;
    float4 v = ((const float4*)x)[i];
    __nv_bfloat16 h0,l0,h1,l1,h2,l2,h3,l3;
    split2(v.x,h0,l0); split2(v.y,h1,l1); split2(v.z,h2,l2); split2(v.w,h3,l3);
    ((__nv_bfloat162*)hi)[i*2]   = __nv_bfloat162(h0,h1);
    ((__nv_bfloat162*)hi)[i*2+1] = __nv_bfloat162(h2,h3);
    ((__nv_bfloat162*)lo)[i*2]   = __nv_bfloat162(l0,l1);
    ((__nv_bfloat162*)lo)[i*2+1] = __nv_bfloat162(l2,l3);
}

// W [K,N] fp32 -> out [N,K] bf16 hi/lo (transpose)
__global__ void cvt_w(const float* __restrict__ W, __nv_bfloat16* __restrict__ bhi,
                      __nv_bfloat16* __restrict__ blo) {
    __shared__ float t[32][33];
    int bx = blockIdx.x * 32;
    int by = blockIdx.y * 32;
    int tx = threadIdx.x, ty = threadIdx.y;    // 32 x 8
    #pragma unroll
    for (int j = 0; j < 32; j += 8)
        t[ty + j][tx] = W[(size_t)(by + ty + j) * DMODEL + bx + tx];
    __syncthreads();
    #pragma unroll
    for (int j = 0; j < 32; j += 8) {
        float v = t[tx][ty + j];
        __nv_bfloat16 h, l; split2(v, h, l);
        size_t o = (size_t)(bx + ty + j) * DMODEL + by + tx;
        bhi[o] = h; blo[o] = l;
    }
}

// ---------------------------------------------------------------------------
// mma.sync bf16 GEMM: C[4096,1024] = A @ W + bias (hi/lo, 3 passes)
// CTA: 128x128, 8 warps (2x4), warp tile 64x32, BK=32, 2-stage cp.async.
// smem rows padded to 80B (40 bf16) -> conflict-free ldmatrix.
// ---------------------------------------------------------------------------
#define BKK 32
#define PADE 40                      // row stride in bf16 elems (80 B)
#define MAT_BYTES (128 * PADE * 2)   // 10240
#define STG_BYTES (4 * MAT_BYTES)    // Ah, Al, Bh, Bl = 40960
#define NIT (DMODEL / BKK)           // 32

template<bool SPLIT>
__global__ __launch_bounds__(256)
void tcgemm(const __nv_bfloat16* __restrict__ Ahi, const __nv_bfloat16* __restrict__ Alo,
            const __nv_bfloat16* __restrict__ Bhi, const __nv_bfloat16* __restrict__ Blo,
            const float* __restrict__ bias, float* __restrict__ C)
{
    extern __shared__ __align__(128) char smem[];
    const uint32_t sb = smem_u32(smem);
    const int tid = threadIdx.x, wid = tid >> 5, lane = tid & 31;
    const int bm = blockIdx.y * 128, bn = blockIdx.x * 128;
    const int wm = wid >> 2, wn = wid & 3;          // 2 x 4 warp grid
    const int m_base = wm * 64, n_base = wn * 32;

    float acc[4][4][4];
    #pragma unroll
    for (int i = 0; i < 4; i++)
        #pragma unroll
        for (int j = 0; j < 4; j++)
            #pragma unroll
            for (int r = 0; r < 4; r++) acc[i][j][r] = 0.0f;

    // ---- stage loader: 2048 16B chunks / 256 threads = 8 per thread ----
    auto load_stage = [&](int stg, int k0) {
        const uint32_t base = sb + stg * STG_BYTES;
        #pragma unroll
        for (int arr = 0; arr < 4; arr++) {
            const __nv_bfloat16* src = (arr == 0) ? Ahi : (arr == 1) ? Alo
                                     : (arr == 2) ? Bhi : Blo;
            const int rowbase = (arr < 2) ? bm : bn;
            #pragma unroll
            for (int i = 0; i < 2; i++) {
                int id = tid + i * 256;              // 0..511
                int r = id >> 2, c4 = id & 3;        // 128 rows x 4 chunks
                const void* g = src + (size_t)(rowbase + r) * DMODEL + k0 + c4 * 8;
                cpasync16(base + arr * MAT_BYTES + r * (PADE * 2) + c4 * 16, g);
            }
        }
        cp_commit();
    };

    load_stage(0, 0);

    // lane-invariant fragment address pieces
    const int a_row_l = lane & 15, a_k_l = (lane >> 4) << 3;

    for (int it = 0; it < NIT; it++) {
        const int stg = it & 1;
        if (it + 1 < NIT) { load_stage(stg ^ 1, (it + 1) * BKK); cp_wait1(); }
        else              { cp_wait0(); }
        __syncthreads();

        const uint32_t sAh = sb + stg * STG_BYTES;
        const uint32_t sAl = sAh + MAT_BYTES;
        const uint32_t sBh = sAh + 2 * MAT_BYTES;
        const uint32_t sBl = sAh + 3 * MAT_BYTES;

        #pragma unroll
        for (int kk = 0; kk < BKK; kk += 16) {
            uint32_t Ah[4][4], Al[4][4], Bh[4][2], Bl[4][2];
            #pragma unroll
            for (int i = 0; i < 4; i++) {
                uint32_t off = (uint32_t)((m_base + i * 16 + a_row_l) * (PADE * 2)
                                          + (kk + a_k_l) * 2);
                ldsm4(Ah[i][0], Ah[i][1], Ah[i][2], Ah[i][3], sAh + off);
                ldsm4(Al[i][0], Al[i][1], Al[i][2], Al[i][3], sAl + off);
            }
            #pragma unroll
            for (int p = 0; p < 2; p++) {
                uint32_t off = (uint32_t)((n_base + p * 16 + a_row_l) * (PADE * 2)
                                          + (kk + a_k_l) * 2);
                uint32_t b0, b1, b2, b3;
                ldsm4(b0, b1, b2, b3, sBh + off);
                Bh[2*p][0] = b0; Bh[2*p+1][0] = b1; Bh[2*p][1] = b2; Bh[2*p+1][1] = b3;
                ldsm4(b0, b1, b2, b3, sBl + off);
                Bl[2*p][0] = b0; Bl[2*p+1][0] = b1; Bl[2*p][1] = b2; Bl[2*p+1][1] = b3;
            }
            #pragma unroll
            for (int i = 0; i < 4; i++)
                #pragma unroll
                for (int j = 0; j < 4; j++) {
                    mma16816(acc[i][j], Ah[i][0], Ah[i][1], Ah[i][2], Ah[i][3],
                             Bh[j][0], Bh[j][1]);
                    mma16816(acc[i][j], Ah[i][0], Ah[i][1], Ah[i][2], Ah[i][3],
                             Bl[j][0], Bl[j][1]);
                    mma16816(acc[i][j], Al[i][0], Al[i][1], Al[i][2], Al[i][3],
                             Bh[j][0], Bh[j][1]);
                }
        }
        __syncthreads();   // protect stage before the (it+2) load overwrites it
    }

    // ---- epilogue: fragment row g=lane>>2 (+8), cols (lane&3)*2 (+1) ----
    const int fr = lane >> 2, fc = (lane & 3) * 2;
    #pragma unroll
    for (int j = 0; j < 4; j++) {
        const int col = bn + n_base + j * 8 + fc;
        const float b0 = bias[col], b1 = bias[col + 1];
        #pragma unroll
        for (int i = 0; i < 4; i++) {
            const int row = bm + m_base + i * 16 + fr;
            float2 v0 = make_float2(acc[i][j][0] + b0, acc[i][j][1] + b1);
            float2 v1 = make_float2(acc[i][j][2] + b0, acc[i][j][3] + b1);
            if (SPLIT) {
                int bb = row >> 11, h = col >> 6, d0 = col & 63;
                int s0 = row & (SS - 1);
                float* base0 = C + ((size_t)((bb * NH + h) * SS + s0)) * DKH + d0;
                *(float2*)base0 = v0;
                *(float2*)(base0 + 8 * DKH) = v1;
            } else {
                float* base0 = C + (size_t)row * DMODEL + col;
                *(float2*)base0 = v0;
                *(float2*)(base0 + 8 * DMODEL) = v1;
            }
        }
    }
}

// ---------------------------------------------------------------------------
// FFMA-only expf
// ---------------------------------------------------------------------------
__device__ __forceinline__ float fexp(float x) {
    x = fmaxf(x, -80.0f);
    float y  = x * 1.4426950408889634f;
    float t  = y + 12582912.0f;
    float fn = t - 12582912.0f;
    float f  = y - fn;
    int   n  = (int)fn;
    float sc = __int_as_float((n + 127) << 23);
    float p  = 1.3333558146e-3f;
    p = fmaf(p, f, 9.6181291076e-3f);
    p = fmaf(p, f, 5.5504108664e-2f);
    p = fmaf(p, f, 2.4022650696e-1f);
    p = fmaf(p, f, 6.9314718056e-1f);
    p = fmaf(p, f, 1.0f);
    return p * sc;
}

// ---------------------------------------------------------------------------
// Flash attention, fp32 (known-good from R1)
// ---------------------------------------------------------------------------
__global__ __launch_bounds__(256)
void attn64(const float* __restrict__ Qh, const float* __restrict__ Kh,
            const float* __restrict__ Vh, float* __restrict__ ctx)
{
    extern __shared__ float sm[];
    float* Qst = sm;
    float* Kst = sm + 64*65;
    float* Vs  = sm + 2*64*65;
    float* Pst = sm + 3*64*65;

    const int tid = threadIdx.x;
    const int qt = blockIdx.x, h = blockIdx.y, b = blockIdx.z;
    const int ty = tid >> 4, tx = tid & 15;
    const float scale = 0.125f;

    const size_t headoff = ((size_t)(b*NH + h)) * SS * DKH;
    const float* Qg = Qh + headoff + (size_t)qt * 64 * DKH;
    const float* Kg = Kh + headoff;
    const float* Vg = Vh + headoff;

    for (int idx = tid; idx < 64*64; idx += 256) {
        int r = idx >> 6, d = idx & 63;
        Qst[d*65 + r] = Qg[idx];
    }
    __syncthreads();

    float m[4], l[4], O[4][4];
    #pragma unroll
    for (int i = 0; i < 4; i++) {
        m[i] = -1e30f; l[i] = 0.0f;
        #pragma unroll
        for (int j = 0; j < 4; j++) O[i][j] = 0.0f;
    }

    for (int kt = 0; kt < SS/64; kt++) {
        const float* Kt = Kg + (size_t)kt * 64 * DKH;
        const float* Vt = Vg + (size_t)kt * 64 * DKH;
        for (int idx = tid; idx < 64*64; idx += 256) {
            int c = idx >> 6, d = idx & 63;
            Kst[d*65 + c] = Kt[idx];
            Vs[c*65 + d]  = Vt[idx];
        }
        __syncthreads();

        float s4[4][4];
        #pragma unroll
        for (int i = 0; i < 4; i++)
            #pragma unroll
            for (int j = 0; j < 4; j++) s4[i][j] = 0.0f;

        #pragma unroll 4
        for (int d = 0; d < 64; d++) {
            float ra[4], rb[4];
            #pragma unroll
            for (int i = 0; i < 4; i++) ra[i] = Qst[d*65 + ty*4 + i];
            #pragma unroll
            for (int j = 0; j < 4; j++) rb[j] = Kst[d*65 + tx*4 + j];
            #pragma unroll
            for (int i = 0; i < 4; i++)
                #pragma unroll
                for (int j = 0; j < 4; j++)
                    s4[i][j] = fmaf(ra[i], rb[j], s4[i][j]);
        }

        #pragma unroll
        for (int i = 0; i < 4; i++) {
            float tm = -1e30f;
            #pragma unroll
            for (int j = 0; j < 4; j++) {
                s4[i][j] *= scale;
                tm = fmaxf(tm, s4[i][j]);
            }
            #pragma unroll
            for (int off = 8; off >= 1; off >>= 1)
                tm = fmaxf(tm, __shfl_xor_sync(0xffffffffu, tm, off));
            float mn = fmaxf(m[i], tm);
            float ps = 0.0f;
            #pragma unroll
            for (int j = 0; j < 4; j++) {
                float p = fexp(s4[i][j] - mn);
                s4[i][j] = p;
                ps += p;
            }
            #pragma unroll
            for (int off = 8; off >= 1; off >>= 1)
                ps += __shfl_xor_sync(0xffffffffu, ps, off);
            float fac = fexp(m[i] - mn);
            l[i] = l[i]*fac + ps;
            m[i] = mn;
            #pragma unroll
            for (int j = 0; j < 4; j++) O[i][j] *= fac;
            #pragma unroll
            for (int j = 0; j < 4; j++)
                Pst[(tx*4 + j)*65 + ty*4 + i] = s4[i][j];
        }
        __syncthreads();

        #pragma unroll 4
        for (int c = 0; c < 64; c++) {
            float rp[4], rv[4];
            #pragma unroll
            for (int i = 0; i < 4; i++) rp[i] = Pst[c*65 + ty*4 + i];
            #pragma unroll
            for (int j = 0; j < 4; j++) rv[j] = Vs[c*65 + tx*4 + j];
            #pragma unroll
            for (int i = 0; i < 4; i++)
                #pragma unroll
                for (int j = 0; j < 4; j++)
                    O[i][j] = fmaf(rp[i], rv[j], O[i][j]);
        }
        __syncthreads();
    }

    #pragma unroll
    for (int i = 0; i < 4; i++) {
        float inv = 1.0f / l[i];
        int s = qt*64 + ty*4 + i;
        float* dst = ctx + ((size_t)(b*SS + s)) * DMODEL + h*DKH + tx*4;
        *(float4*)dst = make_float4(O[i][0]*inv, O[i][1]*inv, O[i][2]*inv, O[i][3]*inv);
    }
}

// ---------------------------------------------------------------------------
extern "C" void kernel_launch(void* const* d_in, const int* in_sizes, int n_in,
                              void* d_out, int out_size)
{
    const float* q  = (const float*)d_in[0];
    const float* k  = (const float*)d_in[1];
    const float* v  = (const float*)d_in[2];
    const float* Wq = (const float*)d_in[3];
    const float* bq = (const float*)d_in[4];
    const float* Wk = (const float*)d_in[5];
    const float* bk = (const float*)d_in[6];
    const float* Wv = (const float*)d_in[7];
    const float* bv = (const float*)d_in[8];
    const float* Wo = (const float*)d_in[9];
    const float* bo = (const float*)d_in[10];
    float* out = (float*)d_out;

    float *Qh, *Kh, *Vh, *ctx;
    __nv_bfloat16 *Ahi, *Alo, *Bhi, *Blo;
    cudaGetSymbolAddress((void**)&Qh,  g_Qh);
    cudaGetSymbolAddress((void**)&Kh,  g_Kh);
    cudaGetSymbolAddress((void**)&Vh,  g_Vh);
    cudaGetSymbolAddress((void**)&ctx, g_ctx);
    cudaGetSymbolAddress((void**)&Ahi, g_Ahi);
    cudaGetSymbolAddress((void**)&Alo, g_Alo);
    cudaGetSymbolAddress((void**)&Bhi, g_Bhi);
    cudaGetSymbolAddress((void**)&Blo, g_Blo);

    const int asmem = 4 * 64 * 65 * (int)sizeof(float);
    cudaFuncSetAttribute(attn64, cudaFuncAttributeMaxDynamicSharedMemorySize, asmem);
    const int gsmem = 2 * STG_BYTES;   // 81920
    cudaFuncSetAttribute(tcgemm<true>,  cudaFuncAttributeMaxDynamicSharedMemorySize, gsmem);
    cudaFuncSetAttribute(tcgemm<false>, cudaFuncAttributeMaxDynamicSharedMemorySize, gsmem);

    dim3 cg(MTOT * DMODEL / 4 / 256);
    dim3 wg(DMODEL / 32, DMODEL / 32);
    dim3 wb(32, 8);
    dim3 gg(DMODEL / 128, MTOT / 128);     // (8, 32)

    cvt_act<<<cg, 256>>>(q, Ahi, Alo, MTOT * DMODEL / 4);
    cvt_w<<<wg, wb>>>(Wq, Bhi, Blo);
    tcgemm<true><<<gg, 256, gsmem>>>(Ahi, Alo, Bhi, Blo, bq, Qh);

    cvt_act<<<cg, 256>>>(k, Ahi, Alo, MTOT * DMODEL / 4);
    cvt_w<<<wg, wb>>>(Wk, Bhi, Blo);
    tcgemm<true><<<gg, 256, gsmem>>>(Ahi, Alo, Bhi, Blo, bk, Kh);

    cvt_act<<<cg, 256>>>(v, Ahi, Alo, MTOT * DMODEL / 4);
    cvt_w<<<wg, wb>>>(Wv, Bhi, Blo);
    tcgemm<true><<<gg, 256, gsmem>>>(Ahi, Alo, Bhi, Blo, bv, Vh);

    attn64<<<dim3(SS/64, NH, NB), 256, asmem>>>(Qh, Kh, Vh, ctx);

    cvt_act<<<cg, 256>>>(ctx, Ahi, Alo, MTOT * DMODEL / 4);
    cvt_w<<<wg, wb>>>(Wo, Bhi, Blo);
    tcgemm<false><<<gg, 256, gsmem>>>(Ahi, Alo, Bhi, Blo, bo, out);
}

// round 5
// speedup vs baseline: 2.3690x; 1.9324x over previous
#include <cuda_runtime.h>
#include <cuda_bf16.h>
#include <math.h>
#include <cstdint>

// Problem constants
#define NB   2
#define SS   2048
#define DMODEL 1024
#define NH   16
#define DKH  64
#define MTOT (NB*SS)    // 4096

// ---------------- scratch (no allocs allowed) ----------------
__device__ float g_ctx[MTOT*DMODEL];
__device__ __nv_bfloat16 g_Ahi[MTOT*DMODEL];   // activation hi/lo (reused per GEMM)
__device__ __nv_bfloat16 g_Alo[MTOT*DMODEL];
__device__ __nv_bfloat16 g_Bhi[DMODEL*DMODEL]; // weight^T [N][K] hi/lo
__device__ __nv_bfloat16 g_Blo[DMODEL*DMODEL];
__device__ __nv_bfloat16 g_Qhi[NB*NH*SS*DKH];  // split-head projection outputs
__device__ __nv_bfloat16 g_Qlo[NB*NH*SS*DKH];
__device__ __nv_bfloat16 g_Khi[NB*NH*SS*DKH];
__device__ __nv_bfloat16 g_Klo[NB*NH*SS*DKH];
__device__ __nv_bfloat16 g_Vhi[NB*NH*SS*DKH];
__device__ __nv_bfloat16 g_Vlo[NB*NH*SS*DKH];

// ---------------- PTX helpers (baseline ISA only) --------------
__device__ __forceinline__ uint32_t smem_u32(const void* p) {
    uint32_t a;
    asm("{ .reg .u64 t; cvta.to.shared.u64 t, %1; cvt.u32.u64 %0, t; }" : "=r"(a) : "l"(p));
    return a;
}
__device__ __forceinline__ void cpasync16(uint32_t dst, const void* src) {
    asm volatile("cp.async.cg.shared.global [%0], [%1], 16;" :: "r"(dst), "l"(src));
}
__device__ __forceinline__ void cp_commit() { asm volatile("cp.async.commit_group;" ::: "memory"); }
__device__ __forceinline__ void cp_wait1()  { asm volatile("cp.async.wait_group 1;" ::: "memory"); }
__device__ __forceinline__ void cp_wait0()  { asm volatile("cp.async.wait_group 0;" ::: "memory"); }

__device__ __forceinline__ void ldsm4(uint32_t& r0, uint32_t& r1, uint32_t& r2, uint32_t& r3,
                                      uint32_t addr) {
    asm volatile("ldmatrix.sync.aligned.m8n8.x4.shared.b16 {%0,%1,%2,%3}, [%4];"
                 : "=r"(r0), "=r"(r1), "=r"(r2), "=r"(r3) : "r"(addr));
}
__device__ __forceinline__ void ldsm4t(uint32_t& r0, uint32_t& r1, uint32_t& r2, uint32_t& r3,
                                       uint32_t addr) {
    asm volatile("ldmatrix.sync.aligned.m8n8.x4.trans.shared.b16 {%0,%1,%2,%3}, [%4];"
                 : "=r"(r0), "=r"(r1), "=r"(r2), "=r"(r3) : "r"(addr));
}
__device__ __forceinline__ void mma16816(float* c,
                                         uint32_t a0, uint32_t a1, uint32_t a2, uint32_t a3,
                                         uint32_t b0, uint32_t b1) {
    asm volatile("mma.sync.aligned.m16n8k16.row.col.f32.bf16.bf16.f32 "
                 "{%0,%1,%2,%3}, {%4,%5,%6,%7}, {%8,%9}, {%0,%1,%2,%3};"
                 : "+f"(c[0]), "+f"(c[1]), "+f"(c[2]), "+f"(c[3])
                 : "r"(a0), "r"(a1), "r"(a2), "r"(a3), "r"(b0), "r"(b1));
}

// ---------------- conversions ----------------
__device__ __forceinline__ void split2(float x, __nv_bfloat16& h, __nv_bfloat16& l) {
    h = __float2bfloat16_rn(x);
    l = __float2bfloat16_rn(x - __bfloat162float(h));
}
__device__ __forceinline__ void pack_hl(float x, float y, uint32_t& hi, uint32_t& lo) {
    __nv_bfloat16 hx, lx, hy, ly;
    split2(x, hx, lx); split2(y, hy, ly);
    __nv_bfloat162 th(hx, hy), tl(lx, ly);
    hi = *(uint32_t*)&th; lo = *(uint32_t*)&tl;
}

__global__ void cvt_act(const float* __restrict__ x, __nv_bfloat16* __restrict__ hi,
                        __nv_bfloat16* __restrict__ lo, int n4) {
    int i = blockIdx.x * blockDim.x + threadIdx.x;
    if (i >= n4) return;
    float4 v = ((const float4*)x)[i];
    __nv_bfloat16 h0,l0,h1,l1,h2,l2,h3,l3;
    split2(v.x,h0,l0); split2(v.y,h1,l1); split2(v.z,h2,l2); split2(v.w,h3,l3);
    ((__nv_bfloat162*)hi)[i*2]   = __nv_bfloat162(h0,h1);
    ((__nv_bfloat162*)hi)[i*2+1] = __nv_bfloat162(h2,h3);
    ((__nv_bfloat162*)lo)[i*2]   = __nv_bfloat162(l0,l1);
    ((__nv_bfloat162*)lo)[i*2+1] = __nv_bfloat162(l2,l3);
}

// W [K,N] fp32 -> out [N,K] bf16 hi/lo (transpose)
__global__ void cvt_w(const float* __restrict__ W, __nv_bfloat16* __restrict__ bhi,
                      __nv_bfloat16* __restrict__ blo) {
    __shared__ float t[32][33];
    int bx = blockIdx.x * 32;
    int by = blockIdx.y * 32;
    int tx = threadIdx.x, ty = threadIdx.y;    // 32 x 8
    #pragma unroll
    for (int j = 0; j < 32; j += 8)
        t[ty + j][tx] = W[(size_t)(by + ty + j) * DMODEL + bx + tx];
    __syncthreads();
    #pragma unroll
    for (int j = 0; j < 32; j += 8) {
        float v = t[tx][ty + j];
        __nv_bfloat16 h, l; split2(v, h, l);
        size_t o = (size_t)(bx + ty + j) * DMODEL + by + tx;
        bhi[o] = h; blo[o] = l;
    }
}

// ---------------------------------------------------------------------------
// mma.sync bf16 GEMM (hi/lo, 3 passes). CTA 128x128, 8 warps (2x4), BK=32.
// MODE 0: fp32 output [M,DMODEL].  MODE 1: bf16 hi/lo split-head [B,H,S,Dk].
// ---------------------------------------------------------------------------
#define BKK 32
#define PADE 40
#define MAT_BYTES (128 * PADE * 2)
#define STG_BYTES (4 * MAT_BYTES)
#define NIT (DMODEL / BKK)

template<int MODE>
__global__ __launch_bounds__(256)
void tcgemm(const __nv_bfloat16* __restrict__ Ahi, const __nv_bfloat16* __restrict__ Alo,
            const __nv_bfloat16* __restrict__ Bhi, const __nv_bfloat16* __restrict__ Blo,
            const float* __restrict__ bias, float* __restrict__ C,
            __nv_bfloat16* __restrict__ Chi, __nv_bfloat16* __restrict__ Clo)
{
    extern __shared__ __align__(128) char smem[];
    const uint32_t sb = smem_u32(smem);
    const int tid = threadIdx.x, wid = tid >> 5, lane = tid & 31;
    const int bm = blockIdx.y * 128, bn = blockIdx.x * 128;
    const int wm = wid >> 2, wn = wid & 3;
    const int m_base = wm * 64, n_base = wn * 32;

    float acc[4][4][4];
    #pragma unroll
    for (int i = 0; i < 4; i++)
        #pragma unroll
        for (int j = 0; j < 4; j++)
            #pragma unroll
            for (int r = 0; r < 4; r++) acc[i][j][r] = 0.0f;

    auto load_stage = [&](int stg, int k0) {
        const uint32_t base = sb + stg * STG_BYTES;
        #pragma unroll
        for (int arr = 0; arr < 4; arr++) {
            const __nv_bfloat16* src = (arr == 0) ? Ahi : (arr == 1) ? Alo
                                     : (arr == 2) ? Bhi : Blo;
            const int rowbase = (arr < 2) ? bm : bn;
            #pragma unroll
            for (int i = 0; i < 2; i++) {
                int id = tid + i * 256;
                int r = id >> 2, c4 = id & 3;
                const void* g = src + (size_t)(rowbase + r) * DMODEL + k0 + c4 * 8;
                cpasync16(base + arr * MAT_BYTES + r * (PADE * 2) + c4 * 16, g);
            }
        }
        cp_commit();
    };

    load_stage(0, 0);
    const int a_row_l = lane & 15, a_k_l = (lane >> 4) << 3;

    for (int it = 0; it < NIT; it++) {
        const int stg = it & 1;
        if (it + 1 < NIT) { load_stage(stg ^ 1, (it + 1) * BKK); cp_wait1(); }
        else              { cp_wait0(); }
        __syncthreads();

        const uint32_t sAh = sb + stg * STG_BYTES;
        const uint32_t sAl = sAh + MAT_BYTES;
        const uint32_t sBh = sAh + 2 * MAT_BYTES;
        const uint32_t sBl = sAh + 3 * MAT_BYTES;

        #pragma unroll
        for (int kk = 0; kk < BKK; kk += 16) {
            uint32_t Ah[4][4], Al[4][4], Bh[4][2], Bl[4][2];
            #pragma unroll
            for (int i = 0; i < 4; i++) {
                uint32_t off = (uint32_t)((m_base + i * 16 + a_row_l) * (PADE * 2)
                                          + (kk + a_k_l) * 2);
                ldsm4(Ah[i][0], Ah[i][1], Ah[i][2], Ah[i][3], sAh + off);
                ldsm4(Al[i][0], Al[i][1], Al[i][2], Al[i][3], sAl + off);
            }
            #pragma unroll
            for (int p = 0; p < 2; p++) {
                uint32_t off = (uint32_t)((n_base + p * 16 + a_row_l) * (PADE * 2)
                                          + (kk + a_k_l) * 2);
                uint32_t b0, b1, b2, b3;
                ldsm4(b0, b1, b2, b3, sBh + off);
                Bh[2*p][0] = b0; Bh[2*p+1][0] = b1; Bh[2*p][1] = b2; Bh[2*p+1][1] = b3;
                ldsm4(b0, b1, b2, b3, sBl + off);
                Bl[2*p][0] = b0; Bl[2*p+1][0] = b1; Bl[2*p][1] = b2; Bl[2*p+1][1] = b3;
            }
            #pragma unroll
            for (int i = 0; i < 4; i++)
                #pragma unroll
                for (int j = 0; j < 4; j++) {
                    mma16816(acc[i][j], Ah[i][0], Ah[i][1], Ah[i][2], Ah[i][3],
                             Bh[j][0], Bh[j][1]);
                    mma16816(acc[i][j], Ah[i][0], Ah[i][1], Ah[i][2], Ah[i][3],
                             Bl[j][0], Bl[j][1]);
                    mma16816(acc[i][j], Al[i][0], Al[i][1], Al[i][2], Al[i][3],
                             Bh[j][0], Bh[j][1]);
                }
        }
        __syncthreads();
    }

    const int fr = lane >> 2, fc = (lane & 3) * 2;
    #pragma unroll
    for (int j = 0; j < 4; j++) {
        const int col = bn + n_base + j * 8 + fc;
        const float b0 = bias[col], b1 = bias[col + 1];
        #pragma unroll
        for (int i = 0; i < 4; i++) {
            const int row = bm + m_base + i * 16 + fr;
            float2 v0 = make_float2(acc[i][j][0] + b0, acc[i][j][1] + b1);
            float2 v1 = make_float2(acc[i][j][2] + b0, acc[i][j][3] + b1);
            if (MODE == 1) {
                int bb = row >> 11, hh = col >> 6, d0 = col & 63;
                int s0 = row & (SS - 1);
                size_t o = ((size_t)((bb * NH + hh) * SS + s0)) * DKH + d0;
                __nv_bfloat16 h0,l0,h1,l1;
                split2(v0.x, h0, l0); split2(v0.y, h1, l1);
                *(__nv_bfloat162*)(Chi + o) = __nv_bfloat162(h0, h1);
                *(__nv_bfloat162*)(Clo + o) = __nv_bfloat162(l0, l1);
                split2(v1.x, h0, l0); split2(v1.y, h1, l1);
                *(__nv_bfloat162*)(Chi + o + 8*DKH) = __nv_bfloat162(h0, h1);
                *(__nv_bfloat162*)(Clo + o + 8*DKH) = __nv_bfloat162(l0, l1);
            } else {
                float* base0 = C + (size_t)row * DMODEL + col;
                *(float2*)base0 = v0;
                *(float2*)(base0 + 8 * DMODEL) = v1;
            }
        }
    }
}

// ---------------------------------------------------------------------------
// FFMA-only expf
// ---------------------------------------------------------------------------
__device__ __forceinline__ float fexp(float x) {
    x = fmaxf(x, -80.0f);
    float y  = x * 1.4426950408889634f;
    float t  = y + 12582912.0f;
    float fn = t - 12582912.0f;
    float f  = y - fn;
    int   n  = (int)fn;
    float sc = __int_as_float((n + 127) << 23);
    float p  = 1.3333558146e-3f;
    p = fmaf(p, f, 9.6181291076e-3f);
    p = fmaf(p, f, 5.5504108664e-2f);
    p = fmaf(p, f, 2.4022650696e-1f);
    p = fmaf(p, f, 6.9314718056e-1f);
    p = fmaf(p, f, 1.0f);
    return p * sc;
}

// ---------------------------------------------------------------------------
// Flash attention on mma.sync bf16 (hi/lo). 128 threads, 4 warps.
// Warp w owns q rows [w*16, w*16+16). Br=Bc=64, Dk=64.
// QK^T: Qhi/lo x Khi/lo, 3 passes. P.V: Phi/lo x Vhi/lo, 3 passes.
// K used as [n=seq][k=dk] via non-trans ldmatrix (proven GEMM-B layout).
// V used via ldmatrix.trans on natural [seq][dk] storage.
// ---------------------------------------------------------------------------
#define AP 72                          // smem row stride (bf16 elems) = 144B
#define TILE_B (64 * AP * 2)           // 9216 bytes per 64x64 tile

__global__ __launch_bounds__(128)
void attnmma(const __nv_bfloat16* __restrict__ Qhi_, const __nv_bfloat16* __restrict__ Qlo_,
             const __nv_bfloat16* __restrict__ Khi_, const __nv_bfloat16* __restrict__ Klo_,
             const __nv_bfloat16* __restrict__ Vhi_, const __nv_bfloat16* __restrict__ Vlo_,
             float* __restrict__ ctx)
{
    extern __shared__ __align__(128) char smem[];
    const uint32_t sb  = smem_u32(smem);
    const uint32_t sQh = sb,              sQl = sb + TILE_B;
    const uint32_t sKh = sb + 2*TILE_B,   sKl = sb + 3*TILE_B;
    const uint32_t sVh = sb + 4*TILE_B,   sVl = sb + 5*TILE_B;

    const int tid = threadIdx.x, w = tid >> 5, lane = tid & 31;
    const int qt = blockIdx.x, h = blockIdx.y, b = blockIdx.z;
    const size_t headoff = ((size_t)(b*NH + h)) * SS * DKH;

    const __nv_bfloat16* Qhg = Qhi_ + headoff + (size_t)qt * 64 * DKH;
    const __nv_bfloat16* Qlg = Qlo_ + headoff + (size_t)qt * 64 * DKH;
    const __nv_bfloat16* Khg = Khi_ + headoff;
    const __nv_bfloat16* Klg = Klo_ + headoff;
    const __nv_bfloat16* Vhg = Vhi_ + headoff;
    const __nv_bfloat16* Vlg = Vlo_ + headoff;

    // load Q tiles (hi+lo): 512 chunks each / 128 threads
    #pragma unroll
    for (int i = 0; i < 4; i++) {
        int c = tid + i * 128;
        int r = c >> 3, c8 = c & 7;
        uint32_t so = (uint32_t)(r * AP + c8 * 8) * 2;
        cpasync16(sQh + so, Qhg + r * 64 + c8 * 8);
        cpasync16(sQl + so, Qlg + r * 64 + c8 * 8);
    }
    cp_commit(); cp_wait0(); __syncthreads();

    // Q register frags: warp w rows w*16.., 4 k-tiles of 16 dk
    const int arow = lane & 15, akl = (lane >> 4) << 3;
    uint32_t qh[4][4], ql[4][4];
    #pragma unroll
    for (int kk = 0; kk < 4; kk++) {
        uint32_t off = (uint32_t)((w * 16 + arow) * AP + kk * 16 + akl) * 2;
        ldsm4(qh[kk][0], qh[kk][1], qh[kk][2], qh[kk][3], sQh + off);
        ldsm4(ql[kk][0], ql[kk][1], ql[kk][2], ql[kk][3], sQl + off);
    }

    float O[8][4];
    #pragma unroll
    for (int j = 0; j < 8; j++)
        #pragma unroll
        for (int r = 0; r < 4; r++) O[j][r] = 0.0f;
    float mA = -1e30f, mB = -1e30f, lA = 0.0f, lB = 0.0f;

    // trans-ldmatrix lane addressing for V
    const int vkrow = (lane & 7) + ((lane >> 4) << 3);
    const int vncol = ((lane >> 3) & 1) * 8;

    for (int kt = 0; kt < SS / 64; kt++) {
        const size_t toff = (size_t)kt * 64 * DKH;
        #pragma unroll
        for (int i = 0; i < 4; i++) {
            int c = tid + i * 128;
            int r = c >> 3, c8 = c & 7;
            uint32_t so = (uint32_t)(r * AP + c8 * 8) * 2;
            size_t go = toff + r * 64 + c8 * 8;
            cpasync16(sKh + so, Khg + go);
            cpasync16(sKl + so, Klg + go);
            cpasync16(sVh + so, Vhg + go);
            cpasync16(sVl + so, Vlg + go);
        }
        cp_commit(); cp_wait0(); __syncthreads();

        // ---- S = Q K^T (3-pass hi/lo) ----
        float c[8][4];
        #pragma unroll
        for (int j = 0; j < 8; j++)
            #pragma unroll
            for (int r = 0; r < 4; r++) c[j][r] = 0.0f;

        #pragma unroll
        for (int p = 0; p < 4; p++) {
            #pragma unroll
            for (int kk = 0; kk < 4; kk++) {
                uint32_t off = (uint32_t)((p * 16 + arow) * AP + kk * 16 + akl) * 2;
                uint32_t bh0, bh1, bh2, bh3, bl0, bl1, bl2, bl3;
                ldsm4(bh0, bh1, bh2, bh3, sKh + off);
                ldsm4(bl0, bl1, bl2, bl3, sKl + off);
                mma16816(c[2*p],   qh[kk][0], qh[kk][1], qh[kk][2], qh[kk][3], bh0, bh2);
                mma16816(c[2*p+1], qh[kk][0], qh[kk][1], qh[kk][2], qh[kk][3], bh1, bh3);
                mma16816(c[2*p],   qh[kk][0], qh[kk][1], qh[kk][2], qh[kk][3], bl0, bl2);
                mma16816(c[2*p+1], qh[kk][0], qh[kk][1], qh[kk][2], qh[kk][3], bl1, bl3);
                mma16816(c[2*p],   ql[kk][0], ql[kk][1], ql[kk][2], ql[kk][3], bh0, bh2);
                mma16816(c[2*p+1], ql[kk][0], ql[kk][1], ql[kk][2], ql[kk][3], bh1, bh3);
            }
        }

        // ---- online softmax (rows rA = lane>>2, rB = rA+8; quad shfl) ----
        float tmA = -1e30f, tmB = -1e30f;
        #pragma unroll
        for (int j = 0; j < 8; j++) {
            c[j][0] *= 0.125f; c[j][1] *= 0.125f; c[j][2] *= 0.125f; c[j][3] *= 0.125f;
            tmA = fmaxf(tmA, fmaxf(c[j][0], c[j][1]));
            tmB = fmaxf(tmB, fmaxf(c[j][2], c[j][3]));
        }
        tmA = fmaxf(tmA, __shfl_xor_sync(0xffffffffu, tmA, 1));
        tmA = fmaxf(tmA, __shfl_xor_sync(0xffffffffu, tmA, 2));
        tmB = fmaxf(tmB, __shfl_xor_sync(0xffffffffu, tmB, 1));
        tmB = fmaxf(tmB, __shfl_xor_sync(0xffffffffu, tmB, 2));

        float mnA = fmaxf(mA, tmA), mnB = fmaxf(mB, tmB);
        float facA = fexp(mA - mnA), facB = fexp(mB - mnB);
        float psA = 0.0f, psB = 0.0f;
        #pragma unroll
        for (int j = 0; j < 8; j++) {
            c[j][0] = fexp(c[j][0] - mnA); c[j][1] = fexp(c[j][1] - mnA);
            c[j][2] = fexp(c[j][2] - mnB); c[j][3] = fexp(c[j][3] - mnB);
            psA += c[j][0] + c[j][1];
            psB += c[j][2] + c[j][3];
        }
        psA += __shfl_xor_sync(0xffffffffu, psA, 1);
        psA += __shfl_xor_sync(0xffffffffu, psA, 2);
        psB += __shfl_xor_sync(0xffffffffu, psB, 1);
        psB += __shfl_xor_sync(0xffffffffu, psB, 2);
        lA = lA * facA + psA;  mA = mnA;
        lB = lB * facB + psB;  mB = mnB;
        #pragma unroll
        for (int j = 0; j < 8; j++) {
            O[j][0] *= facA; O[j][1] *= facA;
            O[j][2] *= facB; O[j][3] *= facB;
        }

        // ---- P frags (hi/lo): a-tile jp covers seq cols 16*jp.. ----
        uint32_t ah[4][4], al[4][4];
        #pragma unroll
        for (int jp = 0; jp < 4; jp++) {
            pack_hl(c[2*jp][0],   c[2*jp][1],   ah[jp][0], al[jp][0]);
            pack_hl(c[2*jp][2],   c[2*jp][3],   ah[jp][1], al[jp][1]);
            pack_hl(c[2*jp+1][0], c[2*jp+1][1], ah[jp][2], al[jp][2]);
            pack_hl(c[2*jp+1][2], c[2*jp+1][3], ah[jp][3], al[jp][3]);
        }

        // ---- O += P V (3-pass hi/lo) ----
        #pragma unroll
        for (int jp = 0; jp < 4; jp++) {
            #pragma unroll
            for (int dn = 0; dn < 4; dn++) {
                uint32_t off = (uint32_t)((jp * 16 + vkrow) * AP + dn * 16 + vncol) * 2;
                uint32_t vh0, vh1, vh2, vh3, vl0, vl1, vl2, vl3;
                ldsm4t(vh0, vh1, vh2, vh3, sVh + off);
                ldsm4t(vl0, vl1, vl2, vl3, sVl + off);
                mma16816(O[2*dn],   ah[jp][0], ah[jp][1], ah[jp][2], ah[jp][3], vh0, vh2);
                mma16816(O[2*dn+1], ah[jp][0], ah[jp][1], ah[jp][2], ah[jp][3], vh1, vh3);
                mma16816(O[2*dn],   ah[jp][0], ah[jp][1], ah[jp][2], ah[jp][3], vl0, vl2);
                mma16816(O[2*dn+1], ah[jp][0], ah[jp][1], ah[jp][2], ah[jp][3], vl1, vl3);
                mma16816(O[2*dn],   al[jp][0], al[jp][1], al[jp][2], al[jp][3], vh0, vh2);
                mma16816(O[2*dn+1], al[jp][0], al[jp][1], al[jp][2], al[jp][3], vh1, vh3);
            }
        }
        __syncthreads();   // protect K/V smem before next tile load
    }

    // ---- normalize + write ctx [B,S,H*Dk] ----
    const float invA = 1.0f / lA, invB = 1.0f / lB;
    const int rA = lane >> 2, fc = (lane & 3) * 2;
    const int sRow = qt * 64 + w * 16 + rA;
    float* outA = ctx + ((size_t)(b * SS + sRow)) * DMODEL + h * DKH;
    float* outB = outA + (size_t)8 * DMODEL;
    #pragma unroll
    for (int j = 0; j < 8; j++) {
        *(float2*)(outA + j * 8 + fc) = make_float2(O[j][0] * invA, O[j][1] * invA);
        *(float2*)(outB + j * 8 + fc) = make_float2(O[j][2] * invB, O[j][3] * invB);
    }
}

// ---------------------------------------------------------------------------
extern "C" void kernel_launch(void* const* d_in, const int* in_sizes, int n_in,
                              void* d_out, int out_size)
{
    const float* q  = (const float*)d_in[0];
    const float* k  = (const float*)d_in[1];
    const float* v  = (const float*)d_in[2];
    const float* Wq = (const float*)d_in[3];
    const float* bq = (const float*)d_in[4];
    const float* Wk = (const float*)d_in[5];
    const float* bk = (const float*)d_in[6];
    const float* Wv = (const float*)d_in[7];
    const float* bv = (const float*)d_in[8];
    const float* Wo = (const float*)d_in[9];
    const float* bo = (const float*)d_in[10];
    float* out = (float*)d_out;

    float *ctx;
    __nv_bfloat16 *Ahi, *Alo, *Bhi, *Blo, *Qhi, *Qlo, *Khi, *Klo, *Vhi, *Vlo;
    cudaGetSymbolAddress((void**)&ctx, g_ctx);
    cudaGetSymbolAddress((void**)&Ahi, g_Ahi);
    cudaGetSymbolAddress((void**)&Alo, g_Alo);
    cudaGetSymbolAddress((void**)&Bhi, g_Bhi);
    cudaGetSymbolAddress((void**)&Blo, g_Blo);
    cudaGetSymbolAddress((void**)&Qhi, g_Qhi);
    cudaGetSymbolAddress((void**)&Qlo, g_Qlo);
    cudaGetSymbolAddress((void**)&Khi, g_Khi);
    cudaGetSymbolAddress((void**)&Klo, g_Klo);
    cudaGetSymbolAddress((void**)&Vhi, g_Vhi);
    cudaGetSymbolAddress((void**)&Vlo, g_Vlo);

    const int gsmem = 2 * STG_BYTES;   // 81920
    cudaFuncSetAttribute(tcgemm<0>, cudaFuncAttributeMaxDynamicSharedMemorySize, gsmem);
    cudaFuncSetAttribute(tcgemm<1>, cudaFuncAttributeMaxDynamicSharedMemorySize, gsmem);
    const int asmem = 6 * TILE_B;      // 55296
    cudaFuncSetAttribute(attnmma, cudaFuncAttributeMaxDynamicSharedMemorySize, asmem);

    dim3 cg(MTOT * DMODEL / 4 / 256);
    dim3 wg(DMODEL / 32, DMODEL / 32);
    dim3 wb(32, 8);
    dim3 gg(DMODEL / 128, MTOT / 128);

    cvt_act<<<cg, 256>>>(q, Ahi, Alo, MTOT * DMODEL / 4);
    cvt_w<<<wg, wb>>>(Wq, Bhi, Blo);
    tcgemm<1><<<gg, 256, gsmem>>>(Ahi, Alo, Bhi, Blo, bq, nullptr, Qhi, Qlo);

    cvt_act<<<cg, 256>>>(k, Ahi, Alo, MTOT * DMODEL / 4);
    cvt_w<<<wg, wb>>>(Wk, Bhi, Blo);
    tcgemm<1><<<gg, 256, gsmem>>>(Ahi, Alo, Bhi, Blo, bk, nullptr, Khi, Klo);

    cvt_act<<<cg, 256>>>(v, Ahi, Alo, MTOT * DMODEL / 4);
    cvt_w<<<wg, wb>>>(Wv, Bhi, Blo);
    tcgemm<1><<<gg, 256, gsmem>>>(Ahi, Alo, Bhi, Blo, bv, nullptr, Vhi, Vlo);

    attnmma<<<dim3(SS/64, NH, NB), 128, asmem>>>(Qhi, Qlo, Khi, Klo, Vhi, Vlo, ctx);

    cvt_act<<<cg, 256>>>(ctx, Ahi, Alo, MTOT * DMODEL / 4);
    cvt_w<<<wg, wb>>>(Wo, Bhi, Blo);
    tcgemm<0><<<gg, 256, gsmem>>>(Ahi, Alo, Bhi, Blo, bo, out, nullptr, nullptr);
}